// round 12
// baseline (speedup 1.0000x reference)
#include <cuda_runtime.h>
#include <cstdint>

#define VSZ 50257
#define ESZ 1024
#define HSZ 1024
#define BSZ 64
#define TSZ 512
#define G4  4096   // 4*H
#define NCTA 128

#define CHUNK_W 4352          // one h chunk: 64 rows * 68 cols (tf32 words)
#define CHUNK_BYTES 17408
#define NCHUNK 16

// ---------------- scratch (device globals; no allocation allowed) ----------
static __device__ float    g_xw[(size_t)TSZ * BSZ * G4];   // [t*B+b][4H]
static __device__ __align__(16) uint32_t g_ht[4][NCHUNK * CHUNK_W]; // h ring, tf32
static __device__ uint32_t g_htd[BSZ * HSZ];               // dense tf32 final h
static __device__ float    g_h[BSZ * HSZ];                 // final h (fp32)
static __device__ float    g_c[BSZ * HSZ];                 // final c (fp32)
static __device__ __align__(16) unsigned g_pc[NCHUNK];     // per-chunk publish cnt

// ---------------- helpers --------------------------------------------------
__device__ __forceinline__ uint32_t f2tf(float x) {
  uint32_t r;
  asm("cvt.rna.tf32.f32 %0, %1;" : "=r"(r) : "f"(x));
  return r;
}

__device__ __forceinline__ void mma8(float* c, const uint32_t* a, const uint32_t* b) {
  asm volatile(
      "mma.sync.aligned.m16n8k8.row.col.f32.tf32.tf32.f32 "
      "{%0,%1,%2,%3}, {%4,%5,%6,%7}, {%8,%9}, {%0,%1,%2,%3};"
      : "+f"(c[0]), "+f"(c[1]), "+f"(c[2]), "+f"(c[3])
      : "r"(a[0]), "r"(a[1]), "r"(a[2]), "r"(a[3]), "r"(b[0]), "r"(b[1]));
}

__device__ __forceinline__ float sigm(float x) {
  return 1.0f / (1.0f + __expf(-x));
}
__device__ __forceinline__ float tanh_fast(float x) {
  return 1.0f - 2.0f / (__expf(2.0f * x) + 1.0f);
}

__device__ __forceinline__ void bar256() {          // compute warps only
  asm volatile("bar.sync 1, 256;" ::: "memory");
}

__device__ __forceinline__ void wait_ge(volatile unsigned* p, unsigned tgt) {
  int spin = 0;
  while (*p < tgt) { if (++spin > 64) { __nanosleep(32); spin = 0; } }
}

__device__ __forceinline__ void mbar_init(uint32_t a, uint32_t cnt) {
  asm volatile("mbarrier.init.shared.b64 [%0], %1;" :: "r"(a), "r"(cnt) : "memory");
}
__device__ __forceinline__ void mbar_expect_tx(uint32_t a, uint32_t tx) {
  asm volatile("mbarrier.arrive.expect_tx.shared.b64 _, [%0], %1;"
               :: "r"(a), "r"(tx) : "memory");
}
__device__ __forceinline__ void mbar_arrive(uint32_t a) {
  asm volatile("mbarrier.arrive.shared.b64 _, [%0];" :: "r"(a) : "memory");
}
__device__ __forceinline__ void mbar_wait(uint32_t a, uint32_t parity) {
  asm volatile(
      "{\n\t.reg .pred P;\n"
      "W%=:\n\t"
      "mbarrier.try_wait.parity.acquire.cta.shared::cta.b64 P, [%0], %1, 0x989680;\n\t"
      "@P bra D%=;\n\t"
      "bra W%=;\n"
      "D%=:\n\t}"
      :: "r"(a), "r"(parity) : "memory");
}
__device__ __forceinline__ void bulk_g2s(uint32_t dst, const void* src,
                                         uint32_t bytes, uint32_t mbar) {
  asm volatile(
      "cp.async.bulk.shared::cluster.global.mbarrier::complete_tx::bytes "
      "[%0], [%1], %2, [%3];"
      :: "r"(dst), "l"(src), "r"(bytes), "r"(mbar) : "memory");
}

// ---------------- kernel: zero h0 (padded tf32) + publish counters ---------
__global__ void k_zero() {
  int i = blockIdx.x * blockDim.x + threadIdx.x;
  if (i < NCHUNK) g_pc[i] = 0u;
  if (i < NCHUNK * CHUNK_W) g_ht[0][i] = 0u;
}

// ---------------- kernel: pre-GEMM  XW = gather(emb) @ W_ih^T --------------
__global__ __launch_bounds__(256) void k_pre(const int* __restrict__ reviews,
                                             const float* __restrict__ emb,
                                             const float* __restrict__ W_ih) {
  __shared__ uint32_t sA[128][36];
  __shared__ uint32_t sB[128][36];

  const int tid = threadIdx.x;
  const int m0 = blockIdx.y * 128;
  const int n0 = blockIdx.x * 128;
  const int lane = tid & 31, w = tid >> 5;
  const int wm = w >> 1, wn = w & 1;      // 4 x 2
  const int gid = lane >> 2, tig = lane & 3;

  const float* arow[4];
  const float* brow[4];
#pragma unroll
  for (int i = 0; i < 4; i++) {
    int q = tid + i * 256;
    int r = q >> 3;
    int m = m0 + r;
    int b = m & 63, t = m >> 6;
    int tok = reviews[b * TSZ + t];
    arow[i] = emb + (size_t)tok * ESZ + ((q & 7) << 2);
    brow[i] = W_ih + (size_t)(n0 + r) * ESZ + ((q & 7) << 2);
  }

  float acc[2][8][4] = {};

  for (int k0 = 0; k0 < 1024; k0 += 32) {
#pragma unroll
    for (int i = 0; i < 4; i++) {
      int q = tid + i * 256;
      int r = q >> 3, c4 = (q & 7) << 2;
      float4 va = *(const float4*)(arow[i] + k0);
      sA[r][c4 + 0] = f2tf(va.x); sA[r][c4 + 1] = f2tf(va.y);
      sA[r][c4 + 2] = f2tf(va.z); sA[r][c4 + 3] = f2tf(va.w);
      float4 vb = *(const float4*)(brow[i] + k0);
      sB[r][c4 + 0] = f2tf(vb.x); sB[r][c4 + 1] = f2tf(vb.y);
      sB[r][c4 + 2] = f2tf(vb.z); sB[r][c4 + 3] = f2tf(vb.w);
    }
    __syncthreads();
#pragma unroll
    for (int k8 = 0; k8 < 4; k8++) {
      const int kk = k8 * 8;
      uint32_t af[2][4], bf[8][2];
#pragma unroll
      for (int mt = 0; mt < 2; mt++) {
        int rm = wm * 32 + mt * 16;
        af[mt][0] = sA[rm + gid][kk + tig];
        af[mt][1] = sA[rm + gid + 8][kk + tig];
        af[mt][2] = sA[rm + gid][kk + tig + 4];
        af[mt][3] = sA[rm + gid + 8][kk + tig + 4];
      }
#pragma unroll
      for (int nt = 0; nt < 8; nt++) {
        int rn = wn * 64 + nt * 8;
        bf[nt][0] = sB[rn + gid][kk + tig];
        bf[nt][1] = sB[rn + gid][kk + tig + 4];
      }
#pragma unroll
      for (int mt = 0; mt < 2; mt++)
#pragma unroll
        for (int nt = 0; nt < 8; nt++) mma8(acc[mt][nt], af[mt], bf[nt]);
    }
    __syncthreads();
  }

#pragma unroll
  for (int mt = 0; mt < 2; mt++) {
    int r0 = m0 + wm * 32 + mt * 16 + gid;
#pragma unroll
    for (int nt = 0; nt < 8; nt++) {
      int c = n0 + wn * 64 + nt * 8 + tig * 2;
      float* C0 = g_xw + (size_t)r0 * G4 + c;
      float* C1 = g_xw + (size_t)(r0 + 8) * G4 + c;
      C0[0] = acc[mt][nt][0]; C0[1] = acc[mt][nt][1];
      C1[0] = acc[mt][nt][2]; C1[1] = acc[mt][nt][3];
    }
  }
}

// ---------------- kernel: persistent recurrence v9 -------------------------
// Barrier-free: h ring depth 4 + per-chunk publish counters (polled by the
// free-running producer warp 8) give full dataflow ordering. Compute warps
// use named barrier 1 (256 threads). Last-round empty arrivals deferred
// until the flat reduce drains the ring.
#define MBAR_W  32                      // 8 mbarriers (full[4], empty[4])
#define W_WORDS (32 * 1028)
#define RING_W  (4 * CHUNK_W)
#define SG_W    (64 * 36)
#define RSM_BYTES ((MBAR_W + W_WORDS + RING_W + SG_W) * 4)   // 210,560 B

__global__ __launch_bounds__(288) void k_rec(const float* __restrict__ W_hh) {
  extern __shared__ uint32_t sm[];
  uint32_t* sW   = sm + MBAR_W;
  uint32_t* ring = sW + W_WORDS;
  float*    sg   = (float*)(ring + RING_W);

  const int tid = threadIdx.x;
  const int j0 = blockIdx.x * 8;
  const int mychunk = blockIdx.x >> 3;
  const int lane = tid & 31, w = tid >> 5;   // warps 0-7 compute, warp 8 produce
  const int gid = lane >> 2, tig = lane & 3;

  const uint32_t mb_b   = (uint32_t)__cvta_generic_to_shared(sm);
  const uint32_t ring_b = (uint32_t)__cvta_generic_to_shared(ring);

  if (tid == 0) {
#pragma unroll
    for (int s = 0; s < 4; s++) {
      mbar_init(mb_b + s * 8, 1);        // full[s]: tx-based
      mbar_init(mb_b + 32 + s * 8, 8);   // empty[s]: 8 compute-warp arrivals
    }
  }

  // ---- load W_hh slice (32 gate rows x 1024) into SMEM as tf32, once ----
  if (tid < 256) {
#pragma unroll 4
    for (int i = 0; i < 32; i++) {
      int e = tid + i * 256;
      int r = e >> 8, cc = (e & 255) * 4;
      int wrow = (r >> 3) * HSZ + j0 + (r & 7);
      float4 v = *(const float4*)(W_hh + (size_t)wrow * HSZ + cc);
      uint32_t* d = sW + r * 1028 + cc;
      d[0] = f2tf(v.x); d[1] = f2tf(v.y); d[2] = f2tf(v.z); d[3] = f2tf(v.w);
    }
  }
  __syncthreads();   // only block-wide barrier (producer included)

  if (w == 8) {
    // ================= producer warp: fully decoupled =================
    if (lane == 0) {
      for (int t = 0; t < TSZ; t++) {
        const uint32_t* __restrict__ hp = g_ht[t & 3];
        const unsigned ptgt = 8u * (unsigned)t;
        unsigned okmask = 0xFFFFu;
        if (t > 0) {
          okmask = 0u;
          uint4 v0 = __ldcg((const uint4*)&g_pc[0]);
          uint4 v1 = __ldcg((const uint4*)&g_pc[4]);
          uint4 v2 = __ldcg((const uint4*)&g_pc[8]);
          uint4 v3 = __ldcg((const uint4*)&g_pc[12]);
          unsigned v[16] = {v0.x, v0.y, v0.z, v0.w, v1.x, v1.y, v1.z, v1.w,
                            v2.x, v2.y, v2.z, v2.w, v3.x, v3.y, v3.z, v3.w};
#pragma unroll
          for (int c = 0; c < 16; c++)
            if (v[c] >= ptgt) okmask |= 1u << c;
        }
        for (int c = 0; c < NCHUNK; c++) {
          if (!((okmask >> c) & 1u)) wait_ge(&g_pc[c], ptgt);
          const int s = c & 3;
          unsigned U = (unsigned)t * 4u + (unsigned)(c >> 2);
          if (U) mbar_wait(mb_b + 32 + s * 8, (U - 1) & 1);
          mbar_expect_tx(mb_b + s * 8, CHUNK_BYTES);
          bulk_g2s(ring_b + s * CHUNK_BYTES, hp + c * CHUNK_W,
                   CHUNK_BYTES, mb_b + s * 8);
        }
      }
    }
    return;   // producer warp (all lanes) exits; no further collective ops
  }

  // ================= compute warps 0-7 =================
  float creg[2] = {0.0f, 0.0f};

  for (int t = 0; t < TSZ; t++) {
    const float* __restrict__ xwb = g_xw + (size_t)t * BSZ * G4;

    // prefetch this step's xw gate biases (independent DRAM loads)
    float xwp[8];
#pragma unroll
    for (int s = 0; s < 2; s++) {
      int idx = tid + s * 256;
      int b = idx >> 3, jj = idx & 7, j = j0 + jj;
      const float* xw = xwb + (size_t)b * G4;
      xwp[s * 4 + 0] = __ldcs(xw + j);
      xwp[s * 4 + 1] = __ldcs(xw + HSZ + j);
      xwp[s * 4 + 2] = __ldcs(xw + 2 * HSZ + j);
      xwp[s * 4 + 3] = __ldcs(xw + 3 * HSZ + j);
    }

    float4 acc4[4][4];
#pragma unroll
    for (int mt = 0; mt < 4; mt++)
#pragma unroll
      for (int nt = 0; nt < 4; nt++)
        acc4[mt][nt] = make_float4(0.f, 0.f, 0.f, 0.f);

    // ---- k loop: mbarrier-paced ----
    for (int kc = 0; kc < 16; kc++) {
      unsigned U = (unsigned)t * 4u + (unsigned)(kc >> 2);
      mbar_wait(mb_b + (kc & 3) * 8, U & 1);

      const uint32_t* sAc = ring + (kc & 3) * CHUNK_W;
      uint32_t af[4][4], bf[4][2];
      const int kk = w * 8;
      const int kt = kc * 64 + kk;
#pragma unroll
      for (int mt = 0; mt < 4; mt++) {
        int ra = (mt * 16 + gid) * 68 + kk + tig;
        af[mt][0] = sAc[ra];
        af[mt][1] = sAc[ra + 8 * 68];
        af[mt][2] = sAc[ra + 4];
        af[mt][3] = sAc[ra + 8 * 68 + 4];
      }
#pragma unroll
      for (int nt = 0; nt < 4; nt++) {
        int rb = (nt * 8 + gid) * 1028 + kt + tig;
        bf[nt][0] = sW[rb];
        bf[nt][1] = sW[rb + 4];
      }
#pragma unroll
      for (int mt = 0; mt < 4; mt++)
#pragma unroll
        for (int nt = 0; nt < 4; nt++)
          mma8((float*)&acc4[mt][nt], af[mt], bf[nt]);

      // rounds 1-3: release slot at consumption; round 4 deferred (ring
      // doubles as the reduce buffer below)
      if (kc < 12 && lane == 0) mbar_arrive(mb_b + 32 + (kc & 3) * 8);
    }

    bar256();   // (a) rings drained -> reduce buffer

    // ---- flat reduce: all 8 warps dump partial tiles into ring ----
    float* fr = (float*)ring;
#pragma unroll
    for (int mt = 0; mt < 4; mt++)
#pragma unroll
      for (int nt = 0; nt < 4; nt++)
        *(float4*)(fr + w * 2048 + ((mt * 4 + nt) * 32 + lane) * 4)
            = acc4[mt][nt];
    bar256();   // (b)

    // each thread sums 2 tile positions across the 8 warps -> sg [64][36]
#pragma unroll
    for (int pi = 0; pi < 2; pi++) {
      int p = tid * 2 + pi;
      float4 s = *(const float4*)(fr + p * 4);
#pragma unroll
      for (int ww = 1; ww < 8; ww++) {
        float4 v = *(const float4*)(fr + ww * 2048 + p * 4);
        s.x += v.x; s.y += v.y; s.z += v.z; s.w += v.w;
      }
      int mt = p >> 7, nt = (p >> 5) & 3, ln = p & 31;
      int g2 = ln >> 2, t2 = ln & 3;
      int r0 = mt * 16 + g2, c = nt * 8 + t2 * 2;
      *(float2*)(sg + r0 * 36 + c)       = make_float2(s.x, s.y);
      *(float2*)(sg + (r0 + 8) * 36 + c) = make_float2(s.z, s.w);
    }
    bar256();   // (c) reduce reads done -> ring free for producer

    // deferred last-round empty arrivals (8 warps x 4 slots = 8 per slot)
    if (lane == 0) {
#pragma unroll
      for (int s = 0; s < 4; s++) mbar_arrive(mb_b + 32 + s * 8);
    }

    // fused LSTM pointwise; c in registers; h written to ring buffer t+1
    uint32_t* __restrict__ hn = g_ht[(t + 1) & 3];
#pragma unroll
    for (int s = 0; s < 2; s++) {
      int idx = tid + s * 256;
      int b = idx >> 3, jj = idx & 7, j = j0 + jj;
      float iv = sg[b * 36 + jj]      + xwp[s * 4 + 0];
      float fv = sg[b * 36 + 8 + jj]  + xwp[s * 4 + 1];
      float gv = sg[b * 36 + 16 + jj] + xwp[s * 4 + 2];
      float ov = sg[b * 36 + 24 + jj] + xwp[s * 4 + 3];
      float c2 = sigm(fv) * creg[s] + sigm(iv) * tanh_fast(gv);
      float h2 = sigm(ov) * tanh_fast(c2);
      creg[s] = c2;
      uint32_t htv = f2tf(h2);
      __stcg(hn + (j >> 6) * CHUNK_W + b * 68 + (j & 63), htv);
      if (t == TSZ - 1) {
        g_htd[b * HSZ + j] = htv;
        g_h[b * HSZ + j] = h2;
        g_c[b * HSZ + j] = c2;
      }
    }

    bar256();   // (d) all h stores of this CTA done
    if (tid == 0) {
      __threadfence();
      atomicAdd(&g_pc[mychunk], 1u);   // publish: chunk ready for step t+1
    }
  }
}

// ---------------- kernel: classifier  logits = h @ W_cls^T + b -------------
__global__ __launch_bounds__(256) void k_cls(const float* __restrict__ W_cls,
                                             const float* __restrict__ b_cls,
                                             float* __restrict__ out) {
  __shared__ uint32_t sA[64][36];
  __shared__ uint32_t sB[128][36];
  const int tid = threadIdx.x;
  const int n0 = blockIdx.x * 128;
  const uint32_t* __restrict__ A = g_htd;   // final h, dense tf32

  const int lane = tid & 31, w = tid >> 5;
  const int wm = w >> 2, wn = w & 3;
  const int gid = lane >> 2, tig = lane & 3;

  const uint32_t* arow[2];
  const float* brow[4];
#pragma unroll
  for (int i = 0; i < 2; i++) {
    int q = tid + i * 256;
    int r = q >> 3;
    arow[i] = A + (size_t)r * HSZ + ((q & 7) << 2);
  }
#pragma unroll
  for (int i = 0; i < 4; i++) {
    int q = tid + i * 256;
    int r = q >> 3;
    int n = n0 + r; if (n > VSZ - 1) n = VSZ - 1;
    brow[i] = W_cls + (size_t)n * HSZ + ((q & 7) << 2);
  }

  float acc[2][4][4] = {};

  for (int k0 = 0; k0 < 1024; k0 += 32) {
#pragma unroll
    for (int i = 0; i < 2; i++) {
      int q = tid + i * 256;
      int r = q >> 3, c4 = (q & 7) << 2;
      uint4 va = *(const uint4*)(arow[i] + k0);
      sA[r][c4 + 0] = va.x; sA[r][c4 + 1] = va.y;
      sA[r][c4 + 2] = va.z; sA[r][c4 + 3] = va.w;
    }
#pragma unroll
    for (int i = 0; i < 4; i++) {
      int q = tid + i * 256;
      int r = q >> 3, c4 = (q & 7) << 2;
      float4 vb = *(const float4*)(brow[i] + k0);
      sB[r][c4 + 0] = f2tf(vb.x); sB[r][c4 + 1] = f2tf(vb.y);
      sB[r][c4 + 2] = f2tf(vb.z); sB[r][c4 + 3] = f2tf(vb.w);
    }
    __syncthreads();
#pragma unroll
    for (int k8 = 0; k8 < 4; k8++) {
      const int kk = k8 * 8;
      uint32_t af[2][4], bf[4][2];
#pragma unroll
      for (int mt = 0; mt < 2; mt++) {
        int rm = wm * 32 + mt * 16;
        af[mt][0] = sA[rm + gid][kk + tig];
        af[mt][1] = sA[rm + gid + 8][kk + tig];
        af[mt][2] = sA[rm + gid][kk + tig + 4];
        af[mt][3] = sA[rm + gid + 8][kk + tig + 4];
      }
#pragma unroll
      for (int nt = 0; nt < 4; nt++) {
        int rn = wn * 32 + nt * 8;
        bf[nt][0] = sB[rn + gid][kk + tig];
        bf[nt][1] = sB[rn + gid][kk + tig + 4];
      }
#pragma unroll
      for (int mt = 0; mt < 2; mt++)
#pragma unroll
        for (int nt = 0; nt < 4; nt++) mma8(acc[mt][nt], af[mt], bf[nt]);
    }
    __syncthreads();
  }

#pragma unroll
  for (int mt = 0; mt < 2; mt++) {
    int r0 = wm * 32 + mt * 16 + gid;
#pragma unroll
    for (int nt = 0; nt < 4; nt++) {
      int c = n0 + wn * 32 + nt * 8 + tig * 2;
      if (c < VSZ)     out[(size_t)r0 * VSZ + c]           = acc[mt][nt][0] + b_cls[c];
      if (c + 1 < VSZ) out[(size_t)r0 * VSZ + c + 1]       = acc[mt][nt][1] + b_cls[c + 1];
      if (c < VSZ)     out[(size_t)(r0 + 8) * VSZ + c]     = acc[mt][nt][2] + b_cls[c];
      if (c + 1 < VSZ) out[(size_t)(r0 + 8) * VSZ + c + 1] = acc[mt][nt][3] + b_cls[c + 1];
    }
  }
}

// ---------------- kernel: copy final h, c into output ----------------------
__global__ void k_tail(float* __restrict__ out) {
  int i = blockIdx.x * blockDim.x + threadIdx.x;
  const size_t OH = (size_t)BSZ * VSZ;
  if (i < BSZ * HSZ) {
    out[OH + i]             = g_h[i];
    out[OH + BSZ * HSZ + i] = g_c[i];
  }
}

// ---------------- launch ---------------------------------------------------
extern "C" void kernel_launch(void* const* d_in, const int* in_sizes, int n_in,
                              void* d_out, int out_size) {
  const int*   reviews = (const int*)d_in[0];
  const float* emb     = (const float*)d_in[1];
  const float* W_ih    = (const float*)d_in[2];
  const float* W_hh    = (const float*)d_in[3];
  const float* W_cls   = (const float*)d_in[4];
  const float* b_cls   = (const float*)d_in[5];
  float* out = (float*)d_out;

  static bool attr_set = false;
  if (!attr_set) {
    cudaFuncSetAttribute(k_rec, cudaFuncAttributeMaxDynamicSharedMemorySize,
                         RSM_BYTES);
    attr_set = true;
  }

  k_zero<<<(NCHUNK * CHUNK_W + 255) / 256, 256>>>();
  k_pre<<<dim3(G4 / 128, (TSZ * BSZ) / 128), 256>>>(reviews, emb, W_ih);
  k_rec<<<NCTA, 288, RSM_BYTES>>>(W_hh);
  k_cls<<<(VSZ + 127) / 128, 256>>>(W_cls, b_cls, out);
  k_tail<<<(BSZ * HSZ + 255) / 256, 256>>>(out);
}

// round 13
// speedup vs baseline: 1.2352x; 1.2352x over previous
#include <cuda_runtime.h>
#include <cstdint>

#define VSZ 50257
#define ESZ 1024
#define HSZ 1024
#define BSZ 64
#define TSZ 512
#define G4  4096   // 4*H
#define NCTA 128

#define CHUNK_W 4352          // one h chunk: 64 rows * 68 cols (tf32 words)
#define CHUNK_BYTES 17408
#define NCHUNK 16

// ---------------- scratch (device globals; no allocation allowed) ----------
static __device__ float    g_xw[(size_t)TSZ * BSZ * G4];   // [t*B+b][4H]
static __device__ __align__(16) uint32_t g_ht[2][NCHUNK * CHUNK_W]; // padded tf32 h
static __device__ uint32_t g_htd[BSZ * HSZ];               // dense tf32 final h
static __device__ float    g_h[BSZ * HSZ];                 // final h (fp32)
static __device__ float    g_c[BSZ * HSZ];                 // final c (fp32)
static __device__ unsigned g_bar;

// ---------------- helpers --------------------------------------------------
__device__ __forceinline__ uint32_t f2tf(float x) {
  uint32_t r;
  asm("cvt.rna.tf32.f32 %0, %1;" : "=r"(r) : "f"(x));
  return r;
}

__device__ __forceinline__ void mma8(float* c, const uint32_t* a, const uint32_t* b) {
  asm volatile(
      "mma.sync.aligned.m16n8k8.row.col.f32.tf32.tf32.f32 "
      "{%0,%1,%2,%3}, {%4,%5,%6,%7}, {%8,%9}, {%0,%1,%2,%3};"
      : "+f"(c[0]), "+f"(c[1]), "+f"(c[2]), "+f"(c[3])
      : "r"(a[0]), "r"(a[1]), "r"(a[2]), "r"(a[3]), "r"(b[0]), "r"(b[1]));
}

__device__ __forceinline__ float sigm(float x) {
  return 1.0f / (1.0f + __expf(-x));
}
__device__ __forceinline__ float tanh_fast(float x) {
  return 1.0f - 2.0f / (__expf(2.0f * x) + 1.0f);
}

__device__ __forceinline__ void cpa16(uint32_t smem_dst, const void* gsrc) {
  asm volatile("cp.async.cg.shared.global [%0], [%1], 16;"
               :: "r"(smem_dst), "l"(gsrc));
}

__device__ __forceinline__ void mbar_init(uint32_t a, uint32_t cnt) {
  asm volatile("mbarrier.init.shared.b64 [%0], %1;" :: "r"(a), "r"(cnt) : "memory");
}
__device__ __forceinline__ void mbar_expect_tx(uint32_t a, uint32_t tx) {
  asm volatile("mbarrier.arrive.expect_tx.shared.b64 _, [%0], %1;"
               :: "r"(a), "r"(tx) : "memory");
}
__device__ __forceinline__ void mbar_arrive(uint32_t a) {
  asm volatile("mbarrier.arrive.shared.b64 _, [%0];" :: "r"(a) : "memory");
}
__device__ __forceinline__ void mbar_wait(uint32_t a, uint32_t parity) {
  asm volatile(
      "{\n\t.reg .pred P;\n"
      "W%=:\n\t"
      "mbarrier.try_wait.parity.acquire.cta.shared::cta.b64 P, [%0], %1, 0x989680;\n\t"
      "@P bra D%=;\n\t"
      "bra W%=;\n"
      "D%=:\n\t}"
      :: "r"(a), "r"(parity) : "memory");
}
__device__ __forceinline__ void bulk_g2s(uint32_t dst, const void* src,
                                         uint32_t bytes, uint32_t mbar) {
  asm volatile(
      "cp.async.bulk.shared::cluster.global.mbarrier::complete_tx::bytes "
      "[%0], [%1], %2, [%3];"
      :: "r"(dst), "l"(src), "r"(bytes), "r"(mbar) : "memory");
}

// ---------------- kernel: zero h0 (padded tf32) + barrier counter ----------
__global__ void k_zero() {
  int i = blockIdx.x * blockDim.x + threadIdx.x;
  if (i == 0) g_bar = 0u;
  if (i < NCHUNK * CHUNK_W) g_ht[0][i] = 0u;
}

// ---------------- kernel: pre-GEMM v2  XW = gather(emb) @ W_ih^T -----------
// cp.async double-buffered pipeline, raw fp32 in SMEM, tf32 convert at
// fragment load. M=T*B (BM=128), N=4096 (BN=128), K=1024 (BK=32).
#define PRE_BUF_W (128 * 36)                       // one fp32 array, words
#define PRE_SM_BYTES (4 * PRE_BUF_W * 4)           // A0,A1,B0,B1 = 73,728 B

__global__ __launch_bounds__(256) void k_pre(const int* __restrict__ reviews,
                                             const float* __restrict__ emb,
                                             const float* __restrict__ W_ih) {
  extern __shared__ float psm[];
  // layout: A0 | A1 | B0 | B1
  const uint32_t psm_b = (uint32_t)__cvta_generic_to_shared(psm);

  const int tid = threadIdx.x;
  const int m0 = blockIdx.y * 128;
  const int n0 = blockIdx.x * 128;
  const int lane = tid & 31, w = tid >> 5;
  const int wm = w >> 1, wn = w & 1;      // 4 x 2
  const int gid = lane >> 2, tig = lane & 3;

  // per-thread source pointers (4 x 16B per chunk for A and B each)
  const float* arow[4];
  const float* brow[4];
  int dst_off[4];                          // word offset r*36 + (q&7)*4
#pragma unroll
  for (int i = 0; i < 4; i++) {
    int q = tid + i * 256;
    int r = q >> 3;
    int m = m0 + r;
    int b = m & 63, t = m >> 6;
    int tok = reviews[b * TSZ + t];
    arow[i] = emb + (size_t)tok * ESZ + ((q & 7) << 2);
    brow[i] = W_ih + (size_t)(n0 + r) * ESZ + ((q & 7) << 2);
    dst_off[i] = r * 36 + ((q & 7) << 2);
  }

  // prologue: issue chunk 0 into buffer 0
#pragma unroll
  for (int i = 0; i < 4; i++) {
    cpa16(psm_b + dst_off[i] * 4, arow[i]);                          // A0
    cpa16(psm_b + (2 * PRE_BUF_W + dst_off[i]) * 4, brow[i]);        // B0
  }
  asm volatile("cp.async.commit_group;");

  float acc[2][8][4] = {};

  for (int kc = 0; kc < 32; kc++) {
    if (kc < 31) {
      const int buf = (kc + 1) & 1;
      const int k0 = (kc + 1) * 32;
#pragma unroll
      for (int i = 0; i < 4; i++) {
        cpa16(psm_b + (buf * PRE_BUF_W + dst_off[i]) * 4, arow[i] + k0);
        cpa16(psm_b + ((2 + buf) * PRE_BUF_W + dst_off[i]) * 4, brow[i] + k0);
      }
      asm volatile("cp.async.commit_group;");
      asm volatile("cp.async.wait_group 1;");
    } else {
      asm volatile("cp.async.wait_group 0;");
    }
    __syncthreads();   // chunk kc resident for all threads

    const float* sAf = psm + (kc & 1) * PRE_BUF_W;
    const float* sBf = psm + (2 + (kc & 1)) * PRE_BUF_W;

#pragma unroll
    for (int k8 = 0; k8 < 4; k8++) {
      const int kk = k8 * 8;
      uint32_t af[2][4], bf[8][2];
#pragma unroll
      for (int mt = 0; mt < 2; mt++) {
        int rm = wm * 32 + mt * 16;
        af[mt][0] = f2tf(sAf[(rm + gid) * 36 + kk + tig]);
        af[mt][1] = f2tf(sAf[(rm + gid + 8) * 36 + kk + tig]);
        af[mt][2] = f2tf(sAf[(rm + gid) * 36 + kk + tig + 4]);
        af[mt][3] = f2tf(sAf[(rm + gid + 8) * 36 + kk + tig + 4]);
      }
#pragma unroll
      for (int nt = 0; nt < 8; nt++) {
        int rn = wn * 64 + nt * 8;
        bf[nt][0] = f2tf(sBf[(rn + gid) * 36 + kk + tig]);
        bf[nt][1] = f2tf(sBf[(rn + gid) * 36 + kk + tig + 4]);
      }
#pragma unroll
      for (int mt = 0; mt < 2; mt++)
#pragma unroll
        for (int nt = 0; nt < 8; nt++) mma8(acc[mt][nt], af[mt], bf[nt]);
    }
    __syncthreads();   // compute done -> buffer reusable next iteration
  }

#pragma unroll
  for (int mt = 0; mt < 2; mt++) {
    int r0 = m0 + wm * 32 + mt * 16 + gid;
#pragma unroll
    for (int nt = 0; nt < 8; nt++) {
      int c = n0 + wn * 64 + nt * 8 + tig * 2;
      float* C0 = g_xw + (size_t)r0 * G4 + c;
      float* C1 = g_xw + (size_t)(r0 + 8) * G4 + c;
      C0[0] = acc[mt][nt][0]; C0[1] = acc[mt][nt][1];
      C1[0] = acc[mt][nt][2]; C1[1] = acc[mt][nt][3];
    }
  }
}

// ---------------- kernel: persistent recurrence (r10, best known) ----------
#define MBAR_W  32                      // 8 mbarriers (full[4], empty[4])
#define W_WORDS (32 * 1028)
#define RING_W  (4 * CHUNK_W)
#define SG_W    (64 * 36)
#define RSM_BYTES ((MBAR_W + W_WORDS + RING_W + SG_W) * 4)   // 210,560 B

__global__ __launch_bounds__(288) void k_rec(const float* __restrict__ W_hh) {
  extern __shared__ uint32_t sm[];
  uint32_t* sW   = sm + MBAR_W;
  uint32_t* ring = sW + W_WORDS;
  float*    sg   = (float*)(ring + RING_W);

  const int tid = threadIdx.x;
  const int j0 = blockIdx.x * 8;
  const int lane = tid & 31, w = tid >> 5;   // warps 0-7 compute, warp 8 produce
  const int gid = lane >> 2, tig = lane & 3;

  const uint32_t mb_b   = (uint32_t)__cvta_generic_to_shared(sm);
  const uint32_t ring_b = (uint32_t)__cvta_generic_to_shared(ring);

  if (tid == 0) {
#pragma unroll
    for (int s = 0; s < 4; s++) {
      mbar_init(mb_b + s * 8, 1);        // full[s]: tx-based
      mbar_init(mb_b + 32 + s * 8, 8);   // empty[s]: 8 compute-warp arrivals
    }
  }

  // ---- load W_hh slice (32 gate rows x 1024) into SMEM as tf32, once ----
  if (tid < 256) {
#pragma unroll 4
    for (int i = 0; i < 32; i++) {
      int e = tid + i * 256;
      int r = e >> 8, cc = (e & 255) * 4;
      int wrow = (r >> 3) * HSZ + j0 + (r & 7);
      float4 v = *(const float4*)(W_hh + (size_t)wrow * HSZ + cc);
      uint32_t* d = sW + r * 1028 + cc;
      d[0] = f2tf(v.x); d[1] = f2tf(v.y); d[2] = f2tf(v.z); d[3] = f2tf(v.w);
    }
  }
  __syncthreads();

  float creg[2] = {0.0f, 0.0f};

  for (int t = 0; t < TSZ; t++) {
    const uint32_t* __restrict__ hp = g_ht[t & 1];
    const float* __restrict__ xwb = g_xw + (size_t)t * BSZ * G4;

    // ---- producer warp: free-run all 16 chunk issuances for this step ----
    if (w == 8) {
      if (lane == 0) {
        for (int c = 0; c < NCHUNK; c++) {
          const int s = c & 3;
          unsigned U = (unsigned)t * 4u + (unsigned)(c >> 2);
          if (U) mbar_wait(mb_b + 32 + s * 8, (U - 1) & 1);
          mbar_expect_tx(mb_b + s * 8, CHUNK_BYTES);
          bulk_g2s(ring_b + s * CHUNK_BYTES, hp + c * CHUNK_W,
                   CHUNK_BYTES, mb_b + s * 8);
        }
      }
    } else {
      // prefetch this step's xw gate biases (independent DRAM loads)
      float xwp[8];
#pragma unroll
      for (int s = 0; s < 2; s++) {
        int idx = tid + s * 256;
        int b = idx >> 3, jj = idx & 7, j = j0 + jj;
        const float* xw = xwb + (size_t)b * G4;
        xwp[s * 4 + 0] = __ldcs(xw + j);
        xwp[s * 4 + 1] = __ldcs(xw + HSZ + j);
        xwp[s * 4 + 2] = __ldcs(xw + 2 * HSZ + j);
        xwp[s * 4 + 3] = __ldcs(xw + 3 * HSZ + j);
      }

      float4 acc4[4][4];
#pragma unroll
      for (int mt = 0; mt < 4; mt++)
#pragma unroll
        for (int nt = 0; nt < 4; nt++)
          acc4[mt][nt] = make_float4(0.f, 0.f, 0.f, 0.f);

      // ---- k loop: mbarrier-paced, no __syncthreads ----
      for (int kc = 0; kc < 16; kc++) {
        unsigned U = (unsigned)t * 4u + (unsigned)(kc >> 2);
        mbar_wait(mb_b + (kc & 3) * 8, U & 1);

        const uint32_t* sAc = ring + (kc & 3) * CHUNK_W;
        uint32_t af[4][4], bf[4][2];
        const int kk = w * 8;
        const int kt = kc * 64 + kk;
#pragma unroll
        for (int mt = 0; mt < 4; mt++) {
          int ra = (mt * 16 + gid) * 68 + kk + tig;
          af[mt][0] = sAc[ra];
          af[mt][1] = sAc[ra + 8 * 68];
          af[mt][2] = sAc[ra + 4];
          af[mt][3] = sAc[ra + 8 * 68 + 4];
        }
#pragma unroll
        for (int nt = 0; nt < 4; nt++) {
          int rb = (nt * 8 + gid) * 1028 + kt + tig;
          bf[nt][0] = sW[rb];
          bf[nt][1] = sW[rb + 4];
        }
#pragma unroll
        for (int mt = 0; mt < 4; mt++)
#pragma unroll
          for (int nt = 0; nt < 4; nt++)
            mma8((float*)&acc4[mt][nt], af[mt], bf[nt]);

        if (lane == 0) mbar_arrive(mb_b + 32 + (kc & 3) * 8);
      }

      __syncthreads();   // (a) rings drained -> reduce buffer

      // ---- flat reduce: all 8 warps dump partial tiles into ring ----
      float* fr = (float*)ring;
#pragma unroll
      for (int mt = 0; mt < 4; mt++)
#pragma unroll
        for (int nt = 0; nt < 4; nt++)
          *(float4*)(fr + w * 2048 + ((mt * 4 + nt) * 32 + lane) * 4)
              = acc4[mt][nt];
      __syncthreads();   // (b)

      // each thread sums 2 tile positions across the 8 warps -> sg [64][36]
#pragma unroll
      for (int pi = 0; pi < 2; pi++) {
        int p = tid * 2 + pi;
        float4 s = *(const float4*)(fr + p * 4);
#pragma unroll
        for (int ww = 1; ww < 8; ww++) {
          float4 v = *(const float4*)(fr + ww * 2048 + p * 4);
          s.x += v.x; s.y += v.y; s.z += v.z; s.w += v.w;
        }
        int mt = p >> 7, nt = (p >> 5) & 3, ln = p & 31;
        int g2 = ln >> 2, t2 = ln & 3;
        int r0 = mt * 16 + g2, c = nt * 8 + t2 * 2;
        *(float2*)(sg + r0 * 36 + c)       = make_float2(s.x, s.y);
        *(float2*)(sg + (r0 + 8) * 36 + c) = make_float2(s.z, s.w);
      }
      __syncthreads();   // (c)

      // fused LSTM pointwise; c in registers; h written as padded tf32
      uint32_t* __restrict__ hn = g_ht[(t + 1) & 1];
#pragma unroll
      for (int s = 0; s < 2; s++) {
        int idx = tid + s * 256;
        int b = idx >> 3, jj = idx & 7, j = j0 + jj;
        float iv = sg[b * 36 + jj]      + xwp[s * 4 + 0];
        float fv = sg[b * 36 + 8 + jj]  + xwp[s * 4 + 1];
        float gv = sg[b * 36 + 16 + jj] + xwp[s * 4 + 2];
        float ov = sg[b * 36 + 24 + jj] + xwp[s * 4 + 3];
        float c2 = sigm(fv) * creg[s] + sigm(iv) * tanh_fast(gv);
        float h2 = sigm(ov) * tanh_fast(c2);
        creg[s] = c2;
        uint32_t htv = f2tf(h2);
        __stcg(hn + (j >> 6) * CHUNK_W + b * 68 + (j & 63), htv);
        if (t == TSZ - 1) {
          g_htd[b * HSZ + j] = htv;
          g_h[b * HSZ + j] = h2;
          g_c[b * HSZ + j] = c2;
        }
      }
    }

    // producer warp: match the compute warps' sync count (a)(b)(c)
    if (w == 8) {
      __syncthreads(); __syncthreads(); __syncthreads();
    }

    // ---- grid barrier: monotonic counter, self-pacing volatile poll ----
    __syncthreads();
    if (tid == 0) {
      __threadfence();
      unsigned arr = atomicAdd(&g_bar, 1u) + 1u;
      unsigned target = (unsigned)(t + 1) * NCTA;
      if (arr != target) {
        while (*((volatile unsigned*)&g_bar) < target) { }
      }
      __threadfence();
    }
    __syncthreads();
  }
}

// ---------------- kernel: classifier  logits = h @ W_cls^T + b -------------
__global__ __launch_bounds__(256) void k_cls(const float* __restrict__ W_cls,
                                             const float* __restrict__ b_cls,
                                             float* __restrict__ out) {
  __shared__ uint32_t sA[64][36];
  __shared__ uint32_t sB[128][36];
  const int tid = threadIdx.x;
  const int n0 = blockIdx.x * 128;
  const uint32_t* __restrict__ A = g_htd;   // final h, dense tf32

  const int lane = tid & 31, w = tid >> 5;
  const int wm = w >> 2, wn = w & 3;
  const int gid = lane >> 2, tig = lane & 3;

  const uint32_t* arow[2];
  const float* brow[4];
#pragma unroll
  for (int i = 0; i < 2; i++) {
    int q = tid + i * 256;
    int r = q >> 3;
    arow[i] = A + (size_t)r * HSZ + ((q & 7) << 2);
  }
#pragma unroll
  for (int i = 0; i < 4; i++) {
    int q = tid + i * 256;
    int r = q >> 3;
    int n = n0 + r; if (n > VSZ - 1) n = VSZ - 1;
    brow[i] = W_cls + (size_t)n * HSZ + ((q & 7) << 2);
  }

  float acc[2][4][4] = {};

  for (int k0 = 0; k0 < 1024; k0 += 32) {
#pragma unroll
    for (int i = 0; i < 2; i++) {
      int q = tid + i * 256;
      int r = q >> 3, c4 = (q & 7) << 2;
      uint4 va = *(const uint4*)(arow[i] + k0);
      sA[r][c4 + 0] = va.x; sA[r][c4 + 1] = va.y;
      sA[r][c4 + 2] = va.z; sA[r][c4 + 3] = va.w;
    }
#pragma unroll
    for (int i = 0; i < 4; i++) {
      int q = tid + i * 256;
      int r = q >> 3, c4 = (q & 7) << 2;
      float4 vb = *(const float4*)(brow[i] + k0);
      sB[r][c4 + 0] = f2tf(vb.x); sB[r][c4 + 1] = f2tf(vb.y);
      sB[r][c4 + 2] = f2tf(vb.z); sB[r][c4 + 3] = f2tf(vb.w);
    }
    __syncthreads();
#pragma unroll
    for (int k8 = 0; k8 < 4; k8++) {
      const int kk = k8 * 8;
      uint32_t af[2][4], bf[4][2];
#pragma unroll
      for (int mt = 0; mt < 2; mt++) {
        int rm = wm * 32 + mt * 16;
        af[mt][0] = sA[rm + gid][kk + tig];
        af[mt][1] = sA[rm + gid + 8][kk + tig];
        af[mt][2] = sA[rm + gid][kk + tig + 4];
        af[mt][3] = sA[rm + gid + 8][kk + tig + 4];
      }
#pragma unroll
      for (int nt = 0; nt < 4; nt++) {
        int rn = wn * 32 + nt * 8;
        bf[nt][0] = sB[rn + gid][kk + tig];
        bf[nt][1] = sB[rn + gid][kk + tig + 4];
      }
#pragma unroll
      for (int mt = 0; mt < 2; mt++)
#pragma unroll
        for (int nt = 0; nt < 4; nt++) mma8(acc[mt][nt], af[mt], bf[nt]);
    }
    __syncthreads();
  }

#pragma unroll
  for (int mt = 0; mt < 2; mt++) {
    int r0 = wm * 32 + mt * 16 + gid;
#pragma unroll
    for (int nt = 0; nt < 4; nt++) {
      int c = n0 + wn * 32 + nt * 8 + tig * 2;
      if (c < VSZ)     out[(size_t)r0 * VSZ + c]           = acc[mt][nt][0] + b_cls[c];
      if (c + 1 < VSZ) out[(size_t)r0 * VSZ + c + 1]       = acc[mt][nt][1] + b_cls[c + 1];
      if (c < VSZ)     out[(size_t)(r0 + 8) * VSZ + c]     = acc[mt][nt][2] + b_cls[c];
      if (c + 1 < VSZ) out[(size_t)(r0 + 8) * VSZ + c + 1] = acc[mt][nt][3] + b_cls[c + 1];
    }
  }
}

// ---------------- kernel: copy final h, c into output ----------------------
__global__ void k_tail(float* __restrict__ out) {
  int i = blockIdx.x * blockDim.x + threadIdx.x;
  const size_t OH = (size_t)BSZ * VSZ;
  if (i < BSZ * HSZ) {
    out[OH + i]             = g_h[i];
    out[OH + BSZ * HSZ + i] = g_c[i];
  }
}

// ---------------- launch ---------------------------------------------------
extern "C" void kernel_launch(void* const* d_in, const int* in_sizes, int n_in,
                              void* d_out, int out_size) {
  const int*   reviews = (const int*)d_in[0];
  const float* emb     = (const float*)d_in[1];
  const float* W_ih    = (const float*)d_in[2];
  const float* W_hh    = (const float*)d_in[3];
  const float* W_cls   = (const float*)d_in[4];
  const float* b_cls   = (const float*)d_in[5];
  float* out = (float*)d_out;

  static bool attr_set = false;
  if (!attr_set) {
    cudaFuncSetAttribute(k_rec, cudaFuncAttributeMaxDynamicSharedMemorySize,
                         RSM_BYTES);
    cudaFuncSetAttribute(k_pre, cudaFuncAttributeMaxDynamicSharedMemorySize,
                         PRE_SM_BYTES);
    attr_set = true;
  }

  k_zero<<<(NCHUNK * CHUNK_W + 255) / 256, 256>>>();
  k_pre<<<dim3(G4 / 128, (TSZ * BSZ) / 128), 256, PRE_SM_BYTES>>>(reviews, emb, W_ih);
  k_rec<<<NCTA, 288, RSM_BYTES>>>(W_hh);
  k_cls<<<(VSZ + 127) / 128, 256>>>(W_cls, b_cls, out);
  k_tail<<<(BSZ * HSZ + 255) / 256, 256>>>(out);
}

// round 14
// speedup vs baseline: 1.3049x; 1.0564x over previous
#include <cuda_runtime.h>
#include <cstdint>

#define VSZ 50257
#define ESZ 1024
#define HSZ 1024
#define BSZ 64
#define TSZ 512
#define G4  4096   // 4*H
#define NCTA 128

#define CHUNK_W 4352          // one h chunk: 64 rows * 68 cols (tf32 words)
#define CHUNK_BYTES 17408
#define NCHUNK 16

// ---------------- scratch (device globals; no allocation allowed) ----------
static __device__ float    g_xw[(size_t)TSZ * BSZ * G4];   // [t*B+b][4H]
static __device__ __align__(16) uint32_t g_ht[2][NCHUNK * CHUNK_W]; // padded tf32 h
static __device__ uint32_t g_htd[BSZ * HSZ];               // dense tf32 final h
static __device__ float    g_h[BSZ * HSZ];                 // final h (fp32)
static __device__ float    g_c[BSZ * HSZ];                 // final c (fp32)
static __device__ unsigned g_bar;

// ---------------- helpers --------------------------------------------------
__device__ __forceinline__ uint32_t f2tf(float x) {
  uint32_t r;
  asm("cvt.rna.tf32.f32 %0, %1;" : "=r"(r) : "f"(x));
  return r;
}

__device__ __forceinline__ void mma8(float* c, const uint32_t* a, const uint32_t* b) {
  asm volatile(
      "mma.sync.aligned.m16n8k8.row.col.f32.tf32.tf32.f32 "
      "{%0,%1,%2,%3}, {%4,%5,%6,%7}, {%8,%9}, {%0,%1,%2,%3};"
      : "+f"(c[0]), "+f"(c[1]), "+f"(c[2]), "+f"(c[3])
      : "r"(a[0]), "r"(a[1]), "r"(a[2]), "r"(a[3]), "r"(b[0]), "r"(b[1]));
}

__device__ __forceinline__ float sigm(float x) {
  return 1.0f / (1.0f + __expf(-x));
}
__device__ __forceinline__ float tanh_fast(float x) {
  return 1.0f - 2.0f / (__expf(2.0f * x) + 1.0f);
}

__device__ __forceinline__ void bar256() {          // compute warps only
  asm volatile("bar.sync 1, 256;" ::: "memory");
}

__device__ __forceinline__ void cpa16(uint32_t smem_dst, const void* gsrc) {
  asm volatile("cp.async.cg.shared.global [%0], [%1], 16;"
               :: "r"(smem_dst), "l"(gsrc));
}

__device__ __forceinline__ void mbar_init(uint32_t a, uint32_t cnt) {
  asm volatile("mbarrier.init.shared.b64 [%0], %1;" :: "r"(a), "r"(cnt) : "memory");
}
__device__ __forceinline__ void mbar_expect_tx(uint32_t a, uint32_t tx) {
  asm volatile("mbarrier.arrive.expect_tx.shared.b64 _, [%0], %1;"
               :: "r"(a), "r"(tx) : "memory");
}
__device__ __forceinline__ void mbar_arrive(uint32_t a) {
  asm volatile("mbarrier.arrive.shared.b64 _, [%0];" :: "r"(a) : "memory");
}
__device__ __forceinline__ void mbar_wait(uint32_t a, uint32_t parity) {
  asm volatile(
      "{\n\t.reg .pred P;\n"
      "W%=:\n\t"
      "mbarrier.try_wait.parity.acquire.cta.shared::cta.b64 P, [%0], %1, 0x989680;\n\t"
      "@P bra D%=;\n\t"
      "bra W%=;\n"
      "D%=:\n\t}"
      :: "r"(a), "r"(parity) : "memory");
}
__device__ __forceinline__ void bulk_g2s(uint32_t dst, const void* src,
                                         uint32_t bytes, uint32_t mbar) {
  asm volatile(
      "cp.async.bulk.shared::cluster.global.mbarrier::complete_tx::bytes "
      "[%0], [%1], %2, [%3];"
      :: "r"(dst), "l"(src), "r"(bytes), "r"(mbar) : "memory");
}

// ---------------- kernel: zero h0 (padded tf32) + barrier counter ----------
__global__ void k_zero() {
  int i = blockIdx.x * blockDim.x + threadIdx.x;
  if (i == 0) g_bar = 0u;
  if (i < NCHUNK * CHUNK_W) g_ht[0][i] = 0u;
}

// ---------------- kernel: pre-GEMM v2  XW = gather(emb) @ W_ih^T -----------
#define PRE_BUF_W (128 * 36)
#define PRE_SM_BYTES (4 * PRE_BUF_W * 4)           // 73,728 B

__global__ __launch_bounds__(256) void k_pre(const int* __restrict__ reviews,
                                             const float* __restrict__ emb,
                                             const float* __restrict__ W_ih) {
  extern __shared__ float psm[];
  const uint32_t psm_b = (uint32_t)__cvta_generic_to_shared(psm);

  const int tid = threadIdx.x;
  const int m0 = blockIdx.y * 128;
  const int n0 = blockIdx.x * 128;
  const int lane = tid & 31, w = tid >> 5;
  const int wm = w >> 1, wn = w & 1;      // 4 x 2
  const int gid = lane >> 2, tig = lane & 3;

  const float* arow[4];
  const float* brow[4];
  int dst_off[4];
#pragma unroll
  for (int i = 0; i < 4; i++) {
    int q = tid + i * 256;
    int r = q >> 3;
    int m = m0 + r;
    int b = m & 63, t = m >> 6;
    int tok = reviews[b * TSZ + t];
    arow[i] = emb + (size_t)tok * ESZ + ((q & 7) << 2);
    brow[i] = W_ih + (size_t)(n0 + r) * ESZ + ((q & 7) << 2);
    dst_off[i] = r * 36 + ((q & 7) << 2);
  }

#pragma unroll
  for (int i = 0; i < 4; i++) {
    cpa16(psm_b + dst_off[i] * 4, arow[i]);
    cpa16(psm_b + (2 * PRE_BUF_W + dst_off[i]) * 4, brow[i]);
  }
  asm volatile("cp.async.commit_group;");

  float acc[2][8][4] = {};

  for (int kc = 0; kc < 32; kc++) {
    if (kc < 31) {
      const int buf = (kc + 1) & 1;
      const int k0 = (kc + 1) * 32;
#pragma unroll
      for (int i = 0; i < 4; i++) {
        cpa16(psm_b + (buf * PRE_BUF_W + dst_off[i]) * 4, arow[i] + k0);
        cpa16(psm_b + ((2 + buf) * PRE_BUF_W + dst_off[i]) * 4, brow[i] + k0);
      }
      asm volatile("cp.async.commit_group;");
      asm volatile("cp.async.wait_group 1;");
    } else {
      asm volatile("cp.async.wait_group 0;");
    }
    __syncthreads();

    const float* sAf = psm + (kc & 1) * PRE_BUF_W;
    const float* sBf = psm + (2 + (kc & 1)) * PRE_BUF_W;

#pragma unroll
    for (int k8 = 0; k8 < 4; k8++) {
      const int kk = k8 * 8;
      uint32_t af[2][4], bf[8][2];
#pragma unroll
      for (int mt = 0; mt < 2; mt++) {
        int rm = wm * 32 + mt * 16;
        af[mt][0] = f2tf(sAf[(rm + gid) * 36 + kk + tig]);
        af[mt][1] = f2tf(sAf[(rm + gid + 8) * 36 + kk + tig]);
        af[mt][2] = f2tf(sAf[(rm + gid) * 36 + kk + tig + 4]);
        af[mt][3] = f2tf(sAf[(rm + gid + 8) * 36 + kk + tig + 4]);
      }
#pragma unroll
      for (int nt = 0; nt < 8; nt++) {
        int rn = wn * 64 + nt * 8;
        bf[nt][0] = f2tf(sBf[(rn + gid) * 36 + kk + tig]);
        bf[nt][1] = f2tf(sBf[(rn + gid) * 36 + kk + tig + 4]);
      }
#pragma unroll
      for (int mt = 0; mt < 2; mt++)
#pragma unroll
        for (int nt = 0; nt < 8; nt++) mma8(acc[mt][nt], af[mt], bf[nt]);
    }
    __syncthreads();
  }

#pragma unroll
  for (int mt = 0; mt < 2; mt++) {
    int r0 = m0 + wm * 32 + mt * 16 + gid;
#pragma unroll
    for (int nt = 0; nt < 8; nt++) {
      int c = n0 + wn * 64 + nt * 8 + tig * 2;
      float* C0 = g_xw + (size_t)r0 * G4 + c;
      float* C1 = g_xw + (size_t)(r0 + 8) * G4 + c;
      C0[0] = acc[mt][nt][0]; C0[1] = acc[mt][nt][1];
      C1[0] = acc[mt][nt][2]; C1[1] = acc[mt][nt][3];
    }
  }
}

// ---------------- kernel: persistent recurrence v10 ------------------------
// r13 structure with the grid barrier converted to producer-only gating:
// compute warps arrive on g_bar after pointwise (no poll, no block sync);
// the decoupled producer warp polls g_bar before issuing each step's chunks.
// All intra-step syncs are compute-only named barriers.
#define MBAR_W  32                      // 8 mbarriers (full[4], empty[4])
#define W_WORDS (32 * 1028)
#define RING_W  (4 * CHUNK_W)
#define SG_W    (64 * 36)
#define RSM_BYTES ((MBAR_W + W_WORDS + RING_W + SG_W) * 4)   // 210,560 B

__global__ __launch_bounds__(288) void k_rec(const float* __restrict__ W_hh) {
  extern __shared__ uint32_t sm[];
  uint32_t* sW   = sm + MBAR_W;
  uint32_t* ring = sW + W_WORDS;
  float*    sg   = (float*)(ring + RING_W);

  const int tid = threadIdx.x;
  const int j0 = blockIdx.x * 8;
  const int lane = tid & 31, w = tid >> 5;   // warps 0-7 compute, warp 8 produce
  const int gid = lane >> 2, tig = lane & 3;

  const uint32_t mb_b   = (uint32_t)__cvta_generic_to_shared(sm);
  const uint32_t ring_b = (uint32_t)__cvta_generic_to_shared(ring);

  if (tid == 0) {
#pragma unroll
    for (int s = 0; s < 4; s++) {
      mbar_init(mb_b + s * 8, 1);        // full[s]: tx-based
      mbar_init(mb_b + 32 + s * 8, 8);   // empty[s]: 8 compute-warp arrivals
    }
  }

  // ---- load W_hh slice (32 gate rows x 1024) into SMEM as tf32, once ----
  if (tid < 256) {
#pragma unroll 4
    for (int i = 0; i < 32; i++) {
      int e = tid + i * 256;
      int r = e >> 8, cc = (e & 255) * 4;
      int wrow = (r >> 3) * HSZ + j0 + (r & 7);
      float4 v = *(const float4*)(W_hh + (size_t)wrow * HSZ + cc);
      uint32_t* d = sW + r * 1028 + cc;
      d[0] = f2tf(v.x); d[1] = f2tf(v.y); d[2] = f2tf(v.z); d[3] = f2tf(v.w);
    }
  }
  __syncthreads();   // only block-wide barrier in the kernel

  if (w == 8) {
    // ================= producer warp: fully decoupled =================
    if (lane == 0) {
      for (int t = 0; t < TSZ; t++) {
        if (t > 0) {
          const unsigned tgt = (unsigned)t * NCTA;
          while (*((volatile unsigned*)&g_bar) < tgt) { }
        }
        const uint32_t* __restrict__ hp = g_ht[t & 1];
        for (int c = 0; c < NCHUNK; c++) {
          const int s = c & 3;
          unsigned U = (unsigned)t * 4u + (unsigned)(c >> 2);
          if (U) mbar_wait(mb_b + 32 + s * 8, (U - 1) & 1);
          mbar_expect_tx(mb_b + s * 8, CHUNK_BYTES);
          bulk_g2s(ring_b + s * CHUNK_BYTES, hp + c * CHUNK_W,
                   CHUNK_BYTES, mb_b + s * 8);
        }
      }
    }
    return;   // warp 8 exits; named barriers use 256 threads
  }

  // ================= compute warps 0-7 =================
  float creg[2] = {0.0f, 0.0f};

  for (int t = 0; t < TSZ; t++) {
    const float* __restrict__ xwb = g_xw + (size_t)t * BSZ * G4;

    // prefetch this step's xw gate biases (independent DRAM loads)
    float xwp[8];
#pragma unroll
    for (int s = 0; s < 2; s++) {
      int idx = tid + s * 256;
      int b = idx >> 3, jj = idx & 7, j = j0 + jj;
      const float* xw = xwb + (size_t)b * G4;
      xwp[s * 4 + 0] = __ldcs(xw + j);
      xwp[s * 4 + 1] = __ldcs(xw + HSZ + j);
      xwp[s * 4 + 2] = __ldcs(xw + 2 * HSZ + j);
      xwp[s * 4 + 3] = __ldcs(xw + 3 * HSZ + j);
    }

    float4 acc4[4][4];
#pragma unroll
    for (int mt = 0; mt < 4; mt++)
#pragma unroll
      for (int nt = 0; nt < 4; nt++)
        acc4[mt][nt] = make_float4(0.f, 0.f, 0.f, 0.f);

    // ---- k loop: mbarrier-paced ----
    for (int kc = 0; kc < 16; kc++) {
      unsigned U = (unsigned)t * 4u + (unsigned)(kc >> 2);
      mbar_wait(mb_b + (kc & 3) * 8, U & 1);

      const uint32_t* sAc = ring + (kc & 3) * CHUNK_W;
      uint32_t af[4][4], bf[4][2];
      const int kk = w * 8;
      const int kt = kc * 64 + kk;
#pragma unroll
      for (int mt = 0; mt < 4; mt++) {
        int ra = (mt * 16 + gid) * 68 + kk + tig;
        af[mt][0] = sAc[ra];
        af[mt][1] = sAc[ra + 8 * 68];
        af[mt][2] = sAc[ra + 4];
        af[mt][3] = sAc[ra + 8 * 68 + 4];
      }
#pragma unroll
      for (int nt = 0; nt < 4; nt++) {
        int rb = (nt * 8 + gid) * 1028 + kt + tig;
        bf[nt][0] = sW[rb];
        bf[nt][1] = sW[rb + 4];
      }
#pragma unroll
      for (int mt = 0; mt < 4; mt++)
#pragma unroll
        for (int nt = 0; nt < 4; nt++)
          mma8((float*)&acc4[mt][nt], af[mt], bf[nt]);

      if (lane == 0) mbar_arrive(mb_b + 32 + (kc & 3) * 8);
    }

    bar256();   // (a) rings drained by all compute warps -> reduce buffer
                // (producer cannot refill until g_bar includes THIS CTA's
                //  arrival, which happens after the reduce + pointwise below)

    // ---- flat reduce: all 8 warps dump partial tiles into ring ----
    float* fr = (float*)ring;
#pragma unroll
    for (int mt = 0; mt < 4; mt++)
#pragma unroll
      for (int nt = 0; nt < 4; nt++)
        *(float4*)(fr + w * 2048 + ((mt * 4 + nt) * 32 + lane) * 4)
            = acc4[mt][nt];
    bar256();   // (b)

    // each thread sums 2 tile positions across the 8 warps -> sg [64][36]
#pragma unroll
    for (int pi = 0; pi < 2; pi++) {
      int p = tid * 2 + pi;
      float4 s = *(const float4*)(fr + p * 4);
#pragma unroll
      for (int ww = 1; ww < 8; ww++) {
        float4 v = *(const float4*)(fr + ww * 2048 + p * 4);
        s.x += v.x; s.y += v.y; s.z += v.z; s.w += v.w;
      }
      int mt = p >> 7, nt = (p >> 5) & 3, ln = p & 31;
      int g2 = ln >> 2, t2 = ln & 3;
      int r0 = mt * 16 + g2, c = nt * 8 + t2 * 2;
      *(float2*)(sg + r0 * 36 + c)       = make_float2(s.x, s.y);
      *(float2*)(sg + (r0 + 8) * 36 + c) = make_float2(s.z, s.w);
    }
    bar256();   // (c)

    // fused LSTM pointwise; c in registers; h written as padded tf32
    uint32_t* __restrict__ hn = g_ht[(t + 1) & 1];
#pragma unroll
    for (int s = 0; s < 2; s++) {
      int idx = tid + s * 256;
      int b = idx >> 3, jj = idx & 7, j = j0 + jj;
      float iv = sg[b * 36 + jj]      + xwp[s * 4 + 0];
      float fv = sg[b * 36 + 8 + jj]  + xwp[s * 4 + 1];
      float gv = sg[b * 36 + 16 + jj] + xwp[s * 4 + 2];
      float ov = sg[b * 36 + 24 + jj] + xwp[s * 4 + 3];
      float c2 = sigm(fv) * creg[s] + sigm(iv) * tanh_fast(gv);
      float h2 = sigm(ov) * tanh_fast(c2);
      creg[s] = c2;
      uint32_t htv = f2tf(h2);
      __stcg(hn + (j >> 6) * CHUNK_W + b * 68 + (j & 63), htv);
      if (t == TSZ - 1) {
        g_htd[b * HSZ + j] = htv;
        g_h[b * HSZ + j] = h2;
        g_c[b * HSZ + j] = c2;
      }
    }

    bar256();   // (d) all compute warps' h stores done
    if (tid == 0) {
      __threadfence();
      atomicAdd(&g_bar, 1u);   // arrive only; producers poll
    }
  }
}

// ---------------- kernel: classifier v2  logits = h @ W_cls^T + b ----------
// cp.async double-buffered; A (g_htd) is already tf32 bits -> copied raw,
// B converted to tf32 at fragment load. 55.3 KB smem -> 4 CTAs/SM.
#define CLS_A_W (64 * 36)
#define CLS_B_W (128 * 36)
#define CLS_SM_BYTES ((2 * CLS_A_W + 2 * CLS_B_W) * 4)   // 55,296 B

__global__ __launch_bounds__(256) void k_cls(const float* __restrict__ W_cls,
                                             const float* __restrict__ b_cls,
                                             float* __restrict__ out) {
  extern __shared__ uint32_t csm[];
  uint32_t* sA = csm;                          // A0 | A1 (tf32 bits)
  float*    sB = (float*)(csm + 2 * CLS_A_W);  // B0 | B1 (raw fp32)
  const uint32_t csm_b = (uint32_t)__cvta_generic_to_shared(csm);
  const uint32_t sB_b  = csm_b + 2 * CLS_A_W * 4;

  const int tid = threadIdx.x;
  const int n0 = blockIdx.x * 128;

  const int lane = tid & 31, w = tid >> 5;
  const int wm = w >> 2, wn = w & 3;
  const int gid = lane >> 2, tig = lane & 3;

  const uint32_t* arow[2]; int adst[2];
  const float* brow[4];    int bdst[4];
#pragma unroll
  for (int i = 0; i < 2; i++) {
    int q = tid + i * 256;
    int r = q >> 3;
    arow[i] = g_htd + (size_t)r * HSZ + ((q & 7) << 2);
    adst[i] = r * 36 + ((q & 7) << 2);
  }
#pragma unroll
  for (int i = 0; i < 4; i++) {
    int q = tid + i * 256;
    int r = q >> 3;
    int n = n0 + r; if (n > VSZ - 1) n = VSZ - 1;
    brow[i] = W_cls + (size_t)n * HSZ + ((q & 7) << 2);
    bdst[i] = r * 36 + ((q & 7) << 2);
  }

  // prologue: chunk 0
#pragma unroll
  for (int i = 0; i < 2; i++) cpa16(csm_b + adst[i] * 4, arow[i]);
#pragma unroll
  for (int i = 0; i < 4; i++) cpa16(sB_b + bdst[i] * 4, brow[i]);
  asm volatile("cp.async.commit_group;");

  float acc[2][4][4] = {};

  for (int kc = 0; kc < 32; kc++) {
    if (kc < 31) {
      const int buf = (kc + 1) & 1;
      const int k0 = (kc + 1) * 32;
#pragma unroll
      for (int i = 0; i < 2; i++)
        cpa16(csm_b + (buf * CLS_A_W + adst[i]) * 4, arow[i] + k0);
#pragma unroll
      for (int i = 0; i < 4; i++)
        cpa16(sB_b + (buf * CLS_B_W + bdst[i]) * 4, brow[i] + k0);
      asm volatile("cp.async.commit_group;");
      asm volatile("cp.async.wait_group 1;");
    } else {
      asm volatile("cp.async.wait_group 0;");
    }
    __syncthreads();

    const uint32_t* a0 = sA + (kc & 1) * CLS_A_W;
    const float*    b0 = sB + (kc & 1) * CLS_B_W;

#pragma unroll
    for (int k8 = 0; k8 < 4; k8++) {
      const int kk = k8 * 8;
      uint32_t af[2][4], bf[4][2];
#pragma unroll
      for (int mt = 0; mt < 2; mt++) {
        int rm = wm * 32 + mt * 16;
        af[mt][0] = a0[(rm + gid) * 36 + kk + tig];
        af[mt][1] = a0[(rm + gid + 8) * 36 + kk + tig];
        af[mt][2] = a0[(rm + gid) * 36 + kk + tig + 4];
        af[mt][3] = a0[(rm + gid + 8) * 36 + kk + tig + 4];
      }
#pragma unroll
      for (int nt = 0; nt < 4; nt++) {
        int rn = wn * 32 + nt * 8;
        bf[nt][0] = f2tf(b0[(rn + gid) * 36 + kk + tig]);
        bf[nt][1] = f2tf(b0[(rn + gid) * 36 + kk + tig + 4]);
      }
#pragma unroll
      for (int mt = 0; mt < 2; mt++)
#pragma unroll
        for (int nt = 0; nt < 4; nt++) mma8(acc[mt][nt], af[mt], bf[nt]);
    }
    __syncthreads();
  }

#pragma unroll
  for (int mt = 0; mt < 2; mt++) {
    int r0 = wm * 32 + mt * 16 + gid;
#pragma unroll
    for (int nt = 0; nt < 4; nt++) {
      int c = n0 + wn * 32 + nt * 8 + tig * 2;
      if (c < VSZ)     out[(size_t)r0 * VSZ + c]           = acc[mt][nt][0] + b_cls[c];
      if (c + 1 < VSZ) out[(size_t)r0 * VSZ + c + 1]       = acc[mt][nt][1] + b_cls[c + 1];
      if (c < VSZ)     out[(size_t)(r0 + 8) * VSZ + c]     = acc[mt][nt][2] + b_cls[c];
      if (c + 1 < VSZ) out[(size_t)(r0 + 8) * VSZ + c + 1] = acc[mt][nt][3] + b_cls[c + 1];
    }
  }
}

// ---------------- kernel: copy final h, c into output ----------------------
__global__ void k_tail(float* __restrict__ out) {
  int i = blockIdx.x * blockDim.x + threadIdx.x;
  const size_t OH = (size_t)BSZ * VSZ;
  if (i < BSZ * HSZ) {
    out[OH + i]             = g_h[i];
    out[OH + BSZ * HSZ + i] = g_c[i];
  }
}

// ---------------- launch ---------------------------------------------------
extern "C" void kernel_launch(void* const* d_in, const int* in_sizes, int n_in,
                              void* d_out, int out_size) {
  const int*   reviews = (const int*)d_in[0];
  const float* emb     = (const float*)d_in[1];
  const float* W_ih    = (const float*)d_in[2];
  const float* W_hh    = (const float*)d_in[3];
  const float* W_cls   = (const float*)d_in[4];
  const float* b_cls   = (const float*)d_in[5];
  float* out = (float*)d_out;

  static bool attr_set = false;
  if (!attr_set) {
    cudaFuncSetAttribute(k_rec, cudaFuncAttributeMaxDynamicSharedMemorySize,
                         RSM_BYTES);
    cudaFuncSetAttribute(k_pre, cudaFuncAttributeMaxDynamicSharedMemorySize,
                         PRE_SM_BYTES);
    cudaFuncSetAttribute(k_cls, cudaFuncAttributeMaxDynamicSharedMemorySize,
                         CLS_SM_BYTES);
    attr_set = true;
  }

  k_zero<<<(NCHUNK * CHUNK_W + 255) / 256, 256>>>();
  k_pre<<<dim3(G4 / 128, (TSZ * BSZ) / 128), 256, PRE_SM_BYTES>>>(reviews, emb, W_ih);
  k_rec<<<NCTA, 288, RSM_BYTES>>>(W_hh);
  k_cls<<<(VSZ + 127) / 128, 256, CLS_SM_BYTES>>>(W_cls, b_cls, out);
  k_tail<<<(BSZ * HSZ + 255) / 256, 256>>>(out);
}

// round 17
// speedup vs baseline: 1.3079x; 1.0023x over previous
#include <cuda_runtime.h>
#include <cstdint>

#define VSZ 50257
#define ESZ 1024
#define HSZ 1024
#define BSZ 64
#define TSZ 512
#define G4  4096   // 4*H
#define NCTA 128

#define CHUNK_W 4352          // one h chunk: 64 rows * 68 cols (tf32 words)
#define CHUNK_BYTES 17408
#define NCHUNK 16

// ---------------- scratch (device globals; no allocation allowed) ----------
static __device__ float    g_xw[(size_t)TSZ * BSZ * G4];   // [t*B+b][4H]
static __device__ __align__(16) uint32_t g_ht[2][NCHUNK * CHUNK_W]; // padded tf32 h
static __device__ uint32_t g_htd[BSZ * HSZ];               // dense tf32 final h
static __device__ float    g_h[BSZ * HSZ];                 // final h (fp32)
static __device__ float    g_c[BSZ * HSZ];                 // final c (fp32)
static __device__ unsigned g_bar;

// ---------------- helpers --------------------------------------------------
__device__ __forceinline__ uint32_t f2tf(float x) {
  uint32_t r;
  asm("cvt.rna.tf32.f32 %0, %1;" : "=r"(r) : "f"(x));
  return r;
}

__device__ __forceinline__ void mma8(float* c, const uint32_t* a, const uint32_t* b) {
  asm volatile(
      "mma.sync.aligned.m16n8k8.row.col.f32.tf32.tf32.f32 "
      "{%0,%1,%2,%3}, {%4,%5,%6,%7}, {%8,%9}, {%0,%1,%2,%3};"
      : "+f"(c[0]), "+f"(c[1]), "+f"(c[2]), "+f"(c[3])
      : "r"(a[0]), "r"(a[1]), "r"(a[2]), "r"(a[3]), "r"(b[0]), "r"(b[1]));
}

__device__ __forceinline__ float sigm(float x) {
  return 1.0f / (1.0f + __expf(-x));
}
__device__ __forceinline__ float tanh_fast(float x) {
  return 1.0f - 2.0f / (__expf(2.0f * x) + 1.0f);
}

__device__ __forceinline__ void bar256() {          // compute warps only
  asm volatile("bar.sync 1, 256;" ::: "memory");
}

__device__ __forceinline__ void cpa16(uint32_t smem_dst, const void* gsrc) {
  asm volatile("cp.async.cg.shared.global [%0], [%1], 16;"
               :: "r"(smem_dst), "l"(gsrc));
}

__device__ __forceinline__ void mbar_init(uint32_t a, uint32_t cnt) {
  asm volatile("mbarrier.init.shared.b64 [%0], %1;" :: "r"(a), "r"(cnt) : "memory");
}
__device__ __forceinline__ void mbar_expect_tx(uint32_t a, uint32_t tx) {
  asm volatile("mbarrier.arrive.expect_tx.shared.b64 _, [%0], %1;"
               :: "r"(a), "r"(tx) : "memory");
}
__device__ __forceinline__ void mbar_arrive(uint32_t a) {
  asm volatile("mbarrier.arrive.shared.b64 _, [%0];" :: "r"(a) : "memory");
}
__device__ __forceinline__ void mbar_wait(uint32_t a, uint32_t parity) {
  asm volatile(
      "{\n\t.reg .pred P;\n"
      "W%=:\n\t"
      "mbarrier.try_wait.parity.acquire.cta.shared::cta.b64 P, [%0], %1, 0x989680;\n\t"
      "@P bra D%=;\n\t"
      "bra W%=;\n"
      "D%=:\n\t}"
      :: "r"(a), "r"(parity) : "memory");
}
__device__ __forceinline__ void bulk_g2s(uint32_t dst, const void* src,
                                         uint32_t bytes, uint32_t mbar) {
  asm volatile(
      "cp.async.bulk.shared::cluster.global.mbarrier::complete_tx::bytes "
      "[%0], [%1], %2, [%3];"
      :: "r"(dst), "l"(src), "r"(bytes), "r"(mbar) : "memory");
}

// ---------------- kernel: zero h0 (padded tf32) + barrier counter ----------
__global__ void k_zero() {
  int i = blockIdx.x * blockDim.x + threadIdx.x;
  if (i == 0) g_bar = 0u;
  if (i < NCHUNK * CHUNK_W) g_ht[0][i] = 0u;
}

// ---------------- kernel: pre-GEMM v2  XW = gather(emb) @ W_ih^T -----------
#define PRE_BUF_W (128 * 36)
#define PRE_SM_BYTES (4 * PRE_BUF_W * 4)           // 73,728 B

__global__ __launch_bounds__(256) void k_pre(const int* __restrict__ reviews,
                                             const float* __restrict__ emb,
                                             const float* __restrict__ W_ih) {
  extern __shared__ float psm[];
  const uint32_t psm_b = (uint32_t)__cvta_generic_to_shared(psm);

  const int tid = threadIdx.x;
  const int m0 = blockIdx.y * 128;
  const int n0 = blockIdx.x * 128;
  const int lane = tid & 31, w = tid >> 5;
  const int wm = w >> 1, wn = w & 1;      // 4 x 2
  const int gid = lane >> 2, tig = lane & 3;

  const float* arow[4];
  const float* brow[4];
  int dst_off[4];
#pragma unroll
  for (int i = 0; i < 4; i++) {
    int q = tid + i * 256;
    int r = q >> 3;
    int m = m0 + r;
    int b = m & 63, t = m >> 6;
    int tok = reviews[b * TSZ + t];
    arow[i] = emb + (size_t)tok * ESZ + ((q & 7) << 2);
    brow[i] = W_ih + (size_t)(n0 + r) * ESZ + ((q & 7) << 2);
    dst_off[i] = r * 36 + ((q & 7) << 2);
  }

#pragma unroll
  for (int i = 0; i < 4; i++) {
    cpa16(psm_b + dst_off[i] * 4, arow[i]);
    cpa16(psm_b + (2 * PRE_BUF_W + dst_off[i]) * 4, brow[i]);
  }
  asm volatile("cp.async.commit_group;");

  float acc[2][8][4] = {};

  for (int kc = 0; kc < 32; kc++) {
    if (kc < 31) {
      const int buf = (kc + 1) & 1;
      const int k0 = (kc + 1) * 32;
#pragma unroll
      for (int i = 0; i < 4; i++) {
        cpa16(psm_b + (buf * PRE_BUF_W + dst_off[i]) * 4, arow[i] + k0);
        cpa16(psm_b + ((2 + buf) * PRE_BUF_W + dst_off[i]) * 4, brow[i] + k0);
      }
      asm volatile("cp.async.commit_group;");
      asm volatile("cp.async.wait_group 1;");
    } else {
      asm volatile("cp.async.wait_group 0;");
    }
    __syncthreads();

    const float* sAf = psm + (kc & 1) * PRE_BUF_W;
    const float* sBf = psm + (2 + (kc & 1)) * PRE_BUF_W;

#pragma unroll
    for (int k8 = 0; k8 < 4; k8++) {
      const int kk = k8 * 8;
      uint32_t af[2][4], bf[8][2];
#pragma unroll
      for (int mt = 0; mt < 2; mt++) {
        int rm = wm * 32 + mt * 16;
        af[mt][0] = f2tf(sAf[(rm + gid) * 36 + kk + tig]);
        af[mt][1] = f2tf(sAf[(rm + gid + 8) * 36 + kk + tig]);
        af[mt][2] = f2tf(sAf[(rm + gid) * 36 + kk + tig + 4]);
        af[mt][3] = f2tf(sAf[(rm + gid + 8) * 36 + kk + tig + 4]);
      }
#pragma unroll
      for (int nt = 0; nt < 8; nt++) {
        int rn = wn * 64 + nt * 8;
        bf[nt][0] = f2tf(sBf[(rn + gid) * 36 + kk + tig]);
        bf[nt][1] = f2tf(sBf[(rn + gid) * 36 + kk + tig + 4]);
      }
#pragma unroll
      for (int mt = 0; mt < 2; mt++)
#pragma unroll
        for (int nt = 0; nt < 8; nt++) mma8(acc[mt][nt], af[mt], bf[nt]);
    }
    __syncthreads();
  }

#pragma unroll
  for (int mt = 0; mt < 2; mt++) {
    int r0 = m0 + wm * 32 + mt * 16 + gid;
#pragma unroll
    for (int nt = 0; nt < 8; nt++) {
      int c = n0 + wn * 64 + nt * 8 + tig * 2;
      float* C0 = g_xw + (size_t)r0 * G4 + c;
      float* C1 = g_xw + (size_t)(r0 + 8) * G4 + c;
      C0[0] = acc[mt][nt][0]; C0[1] = acc[mt][nt][1];
      C1[0] = acc[mt][nt][2]; C1[1] = acc[mt][nt][3];
    }
  }
}

// ---------------- kernel: persistent recurrence (r14 structure) ------------
// Producer-only gating: compute warps arrive on g_bar after pointwise; the
// decoupled producer warp polls g_bar (with backoff) before issuing each
// step's chunks. Intra-step syncs are compute-only named barriers.
#define MBAR_W  32                      // 8 mbarriers (full[4], empty[4])
#define W_WORDS (32 * 1028)
#define RING_W  (4 * CHUNK_W)
#define SG_W    (64 * 36)
#define RSM_BYTES ((MBAR_W + W_WORDS + RING_W + SG_W) * 4)   // 210,560 B

__global__ __launch_bounds__(288) void k_rec(const float* __restrict__ W_hh) {
  extern __shared__ uint32_t sm[];
  uint32_t* sW   = sm + MBAR_W;
  uint32_t* ring = sW + W_WORDS;
  float*    sg   = (float*)(ring + RING_W);

  const int tid = threadIdx.x;
  const int j0 = blockIdx.x * 8;
  const int lane = tid & 31, w = tid >> 5;   // warps 0-7 compute, warp 8 produce
  const int gid = lane >> 2, tig = lane & 3;

  const uint32_t mb_b   = (uint32_t)__cvta_generic_to_shared(sm);
  const uint32_t ring_b = (uint32_t)__cvta_generic_to_shared(ring);

  if (tid == 0) {
#pragma unroll
    for (int s = 0; s < 4; s++) {
      mbar_init(mb_b + s * 8, 1);        // full[s]: tx-based
      mbar_init(mb_b + 32 + s * 8, 8);   // empty[s]: 8 compute-warp arrivals
    }
  }

  // ---- load W_hh slice (32 gate rows x 1024) into SMEM as tf32, once ----
  if (tid < 256) {
#pragma unroll 4
    for (int i = 0; i < 32; i++) {
      int e = tid + i * 256;
      int r = e >> 8, cc = (e & 255) * 4;
      int wrow = (r >> 3) * HSZ + j0 + (r & 7);
      float4 v = *(const float4*)(W_hh + (size_t)wrow * HSZ + cc);
      uint32_t* d = sW + r * 1028 + cc;
      d[0] = f2tf(v.x); d[1] = f2tf(v.y); d[2] = f2tf(v.z); d[3] = f2tf(v.w);
    }
  }
  __syncthreads();   // only block-wide barrier in the kernel

  if (w == 8) {
    // ================= producer warp: fully decoupled =================
    if (lane == 0) {
      for (int t = 0; t < TSZ; t++) {
        if (t > 0) {
          const unsigned tgt = (unsigned)t * NCTA;
          int spin = 0;
          while (*((volatile unsigned*)&g_bar) < tgt) {
            if (++spin > 64) { __nanosleep(32); spin = 0; }
          }
        }
        const uint32_t* __restrict__ hp = g_ht[t & 1];
        for (int c = 0; c < NCHUNK; c++) {
          const int s = c & 3;
          unsigned U = (unsigned)t * 4u + (unsigned)(c >> 2);
          if (U) mbar_wait(mb_b + 32 + s * 8, (U - 1) & 1);
          mbar_expect_tx(mb_b + s * 8, CHUNK_BYTES);
          bulk_g2s(ring_b + s * CHUNK_BYTES, hp + c * CHUNK_W,
                   CHUNK_BYTES, mb_b + s * 8);
        }
      }
    }
    return;   // warp 8 exits; named barriers use 256 threads
  }

  // ================= compute warps 0-7 =================
  float creg[2] = {0.0f, 0.0f};

  for (int t = 0; t < TSZ; t++) {
    const float* __restrict__ xwb = g_xw + (size_t)t * BSZ * G4;

    // prefetch this step's xw gate biases (independent DRAM loads)
    float xwp[8];
#pragma unroll
    for (int s = 0; s < 2; s++) {
      int idx = tid + s * 256;
      int b = idx >> 3, jj = idx & 7, j = j0 + jj;
      const float* xw = xwb + (size_t)b * G4;
      xwp[s * 4 + 0] = __ldcs(xw + j);
      xwp[s * 4 + 1] = __ldcs(xw + HSZ + j);
      xwp[s * 4 + 2] = __ldcs(xw + 2 * HSZ + j);
      xwp[s * 4 + 3] = __ldcs(xw + 3 * HSZ + j);
    }

    float4 acc4[4][4];
#pragma unroll
    for (int mt = 0; mt < 4; mt++)
#pragma unroll
      for (int nt = 0; nt < 4; nt++)
        acc4[mt][nt] = make_float4(0.f, 0.f, 0.f, 0.f);

    // ---- k loop: mbarrier-paced ----
    for (int kc = 0; kc < 16; kc++) {
      unsigned U = (unsigned)t * 4u + (unsigned)(kc >> 2);
      mbar_wait(mb_b + (kc & 3) * 8, U & 1);

      const uint32_t* sAc = ring + (kc & 3) * CHUNK_W;
      uint32_t af[4][4], bf[4][2];
      const int kk = w * 8;
      const int kt = kc * 64 + kk;
#pragma unroll
      for (int mt = 0; mt < 4; mt++) {
        int ra = (mt * 16 + gid) * 68 + kk + tig;
        af[mt][0] = sAc[ra];
        af[mt][1] = sAc[ra + 8 * 68];
        af[mt][2] = sAc[ra + 4];
        af[mt][3] = sAc[ra + 8 * 68 + 4];
      }
#pragma unroll
      for (int nt = 0; nt < 4; nt++) {
        int rb = (nt * 8 + gid) * 1028 + kt + tig;
        bf[nt][0] = sW[rb];
        bf[nt][1] = sW[rb + 4];
      }
#pragma unroll
      for (int mt = 0; mt < 4; mt++)
#pragma unroll
        for (int nt = 0; nt < 4; nt++)
          mma8((float*)&acc4[mt][nt], af[mt], bf[nt]);

      if (lane == 0) mbar_arrive(mb_b + 32 + (kc & 3) * 8);
    }

    bar256();   // (a) rings drained -> reduce buffer (producer gated by g_bar)

    // ---- flat reduce: all 8 warps dump partial tiles into ring ----
    float* fr = (float*)ring;
#pragma unroll
    for (int mt = 0; mt < 4; mt++)
#pragma unroll
      for (int nt = 0; nt < 4; nt++)
        *(float4*)(fr + w * 2048 + ((mt * 4 + nt) * 32 + lane) * 4)
            = acc4[mt][nt];
    bar256();   // (b)

    // each thread sums 2 tile positions across the 8 warps -> sg [64][36]
#pragma unroll
    for (int pi = 0; pi < 2; pi++) {
      int p = tid * 2 + pi;
      float4 s = *(const float4*)(fr + p * 4);
#pragma unroll
      for (int ww = 1; ww < 8; ww++) {
        float4 v = *(const float4*)(fr + ww * 2048 + p * 4);
        s.x += v.x; s.y += v.y; s.z += v.z; s.w += v.w;
      }
      int mt = p >> 7, nt = (p >> 5) & 3, ln = p & 31;
      int g2 = ln >> 2, t2 = ln & 3;
      int r0 = mt * 16 + g2, c = nt * 8 + t2 * 2;
      *(float2*)(sg + r0 * 36 + c)       = make_float2(s.x, s.y);
      *(float2*)(sg + (r0 + 8) * 36 + c) = make_float2(s.z, s.w);
    }
    bar256();   // (c)

    // fused LSTM pointwise; c in registers; h written as padded tf32
    uint32_t* __restrict__ hn = g_ht[(t + 1) & 1];
#pragma unroll
    for (int s = 0; s < 2; s++) {
      int idx = tid + s * 256;
      int b = idx >> 3, jj = idx & 7, j = j0 + jj;
      float iv = sg[b * 36 + jj]      + xwp[s * 4 + 0];
      float fv = sg[b * 36 + 8 + jj]  + xwp[s * 4 + 1];
      float gv = sg[b * 36 + 16 + jj] + xwp[s * 4 + 2];
      float ov = sg[b * 36 + 24 + jj] + xwp[s * 4 + 3];
      float c2 = sigm(fv) * creg[s] + sigm(iv) * tanh_fast(gv);
      float h2 = sigm(ov) * tanh_fast(c2);
      creg[s] = c2;
      uint32_t htv = f2tf(h2);
      __stcg(hn + (j >> 6) * CHUNK_W + b * 68 + (j & 63), htv);
      if (t == TSZ - 1) {
        g_htd[b * HSZ + j] = htv;
        g_h[b * HSZ + j] = h2;
        g_c[b * HSZ + j] = c2;
      }
    }

    bar256();   // (d) all compute warps' h stores done
    if (tid == 0) {
      __threadfence();
      atomicAdd(&g_bar, 1u);   // arrive only; producer polls
    }
  }
}

// ---------------- kernel: classifier v2  logits = h @ W_cls^T + b ----------
#define CLS_A_W (64 * 36)
#define CLS_B_W (128 * 36)
#define CLS_SM_BYTES ((2 * CLS_A_W + 2 * CLS_B_W) * 4)   // 55,296 B

__global__ __launch_bounds__(256) void k_cls(const float* __restrict__ W_cls,
                                             const float* __restrict__ b_cls,
                                             float* __restrict__ out) {
  extern __shared__ uint32_t csm[];
  uint32_t* sA = csm;                          // A0 | A1 (tf32 bits)
  float*    sB = (float*)(csm + 2 * CLS_A_W);  // B0 | B1 (raw fp32)
  const uint32_t csm_b = (uint32_t)__cvta_generic_to_shared(csm);
  const uint32_t sB_b  = csm_b + 2 * CLS_A_W * 4;

  const int tid = threadIdx.x;
  const int n0 = blockIdx.x * 128;

  const int lane = tid & 31, w = tid >> 5;
  const int wm = w >> 2, wn = w & 3;
  const int gid = lane >> 2, tig = lane & 3;

  const uint32_t* arow[2]; int adst[2];
  const float* brow[4];    int bdst[4];
#pragma unroll
  for (int i = 0; i < 2; i++) {
    int q = tid + i * 256;
    int r = q >> 3;
    arow[i] = g_htd + (size_t)r * HSZ + ((q & 7) << 2);
    adst[i] = r * 36 + ((q & 7) << 2);
  }
#pragma unroll
  for (int i = 0; i < 4; i++) {
    int q = tid + i * 256;
    int r = q >> 3;
    int n = n0 + r; if (n > VSZ - 1) n = VSZ - 1;
    brow[i] = W_cls + (size_t)n * HSZ + ((q & 7) << 2);
    bdst[i] = r * 36 + ((q & 7) << 2);
  }

#pragma unroll
  for (int i = 0; i < 2; i++) cpa16(csm_b + adst[i] * 4, arow[i]);
#pragma unroll
  for (int i = 0; i < 4; i++) cpa16(sB_b + bdst[i] * 4, brow[i]);
  asm volatile("cp.async.commit_group;");

  float acc[2][4][4] = {};

  for (int kc = 0; kc < 32; kc++) {
    if (kc < 31) {
      const int buf = (kc + 1) & 1;
      const int k0 = (kc + 1) * 32;
#pragma unroll
      for (int i = 0; i < 2; i++)
        cpa16(csm_b + (buf * CLS_A_W + adst[i]) * 4, arow[i] + k0);
#pragma unroll
      for (int i = 0; i < 4; i++)
        cpa16(sB_b + (buf * CLS_B_W + bdst[i]) * 4, brow[i] + k0);
      asm volatile("cp.async.commit_group;");
      asm volatile("cp.async.wait_group 1;");
    } else {
      asm volatile("cp.async.wait_group 0;");
    }
    __syncthreads();

    const uint32_t* a0 = sA + (kc & 1) * CLS_A_W;
    const float*    b0 = sB + (kc & 1) * CLS_B_W;

#pragma unroll
    for (int k8 = 0; k8 < 4; k8++) {
      const int kk = k8 * 8;
      uint32_t af[2][4], bf[4][2];
#pragma unroll
      for (int mt = 0; mt < 2; mt++) {
        int rm = wm * 32 + mt * 16;
        af[mt][0] = a0[(rm + gid) * 36 + kk + tig];
        af[mt][1] = a0[(rm + gid + 8) * 36 + kk + tig];
        af[mt][2] = a0[(rm + gid) * 36 + kk + tig + 4];
        af[mt][3] = a0[(rm + gid + 8) * 36 + kk + tig + 4];
      }
#pragma unroll
      for (int nt = 0; nt < 4; nt++) {
        int rn = wn * 32 + nt * 8;
        bf[nt][0] = f2tf(b0[(rn + gid) * 36 + kk + tig]);
        bf[nt][1] = f2tf(b0[(rn + gid) * 36 + kk + tig + 4]);
      }
#pragma unroll
      for (int mt = 0; mt < 2; mt++)
#pragma unroll
        for (int nt = 0; nt < 4; nt++) mma8(acc[mt][nt], af[mt], bf[nt]);
    }
    __syncthreads();
  }

#pragma unroll
  for (int mt = 0; mt < 2; mt++) {
    int r0 = wm * 32 + mt * 16 + gid;
#pragma unroll
    for (int nt = 0; nt < 4; nt++) {
      int c = n0 + wn * 32 + nt * 8 + tig * 2;
      if (c < VSZ)     out[(size_t)r0 * VSZ + c]           = acc[mt][nt][0] + b_cls[c];
      if (c + 1 < VSZ) out[(size_t)r0 * VSZ + c + 1]       = acc[mt][nt][1] + b_cls[c + 1];
      if (c < VSZ)     out[(size_t)(r0 + 8) * VSZ + c]     = acc[mt][nt][2] + b_cls[c];
      if (c + 1 < VSZ) out[(size_t)(r0 + 8) * VSZ + c + 1] = acc[mt][nt][3] + b_cls[c + 1];
    }
  }
}

// ---------------- kernel: copy final h, c into output ----------------------
__global__ void k_tail(float* __restrict__ out) {
  int i = blockIdx.x * blockDim.x + threadIdx.x;
  const size_t OH = (size_t)BSZ * VSZ;
  if (i < BSZ * HSZ) {
    out[OH + i]             = g_h[i];
    out[OH + BSZ * HSZ + i] = g_c[i];
  }
}

// ---------------- launch ---------------------------------------------------
extern "C" void kernel_launch(void* const* d_in, const int* in_sizes, int n_in,
                              void* d_out, int out_size) {
  const int*   reviews = (const int*)d_in[0];
  const float* emb     = (const float*)d_in[1];
  const float* W_ih    = (const float*)d_in[2];
  const float* W_hh    = (const float*)d_in[3];
  const float* W_cls   = (const float*)d_in[4];
  const float* b_cls   = (const float*)d_in[5];
  float* out = (float*)d_out;

  static bool attr_set = false;
  if (!attr_set) {
    cudaFuncSetAttribute(k_rec, cudaFuncAttributeMaxDynamicSharedMemorySize,
                         RSM_BYTES);
    cudaFuncSetAttribute(k_pre, cudaFuncAttributeMaxDynamicSharedMemorySize,
                         PRE_SM_BYTES);
    cudaFuncSetAttribute(k_cls, cudaFuncAttributeMaxDynamicSharedMemorySize,
                         CLS_SM_BYTES);
    attr_set = true;
  }

  k_zero<<<(NCHUNK * CHUNK_W + 255) / 256, 256>>>();
  k_pre<<<dim3(G4 / 128, (TSZ * BSZ) / 128), 256, PRE_SM_BYTES>>>(reviews, emb, W_ih);
  k_rec<<<NCTA, 288, RSM_BYTES>>>(W_hh);
  k_cls<<<(VSZ + 127) / 128, 256, CLS_SM_BYTES>>>(W_cls, b_cls, out);
  k_tail<<<(BSZ * HSZ + 255) / 256, 256>>>(out);
}